// round 16
// baseline (speedup 1.0000x reference)
#include <cuda_runtime.h>
#include <cuda_bf16.h>
#include <math.h>

#define NN 100000
#define EDGES 1600000
#define FEAT 256
#define HID 128
#define OUTC 64
#define SCAN_CHUNK 1024
#define MAX_BLK ((NN + SCAN_CHUNK - 1) / SCAN_CHUNK + 1)

// ---------------- scratch (device globals; no allocation allowed) ----------
__device__ __align__(16) float g_dinv[NN];
__device__ __align__(16) int   g_cnt[NN];
__device__ __align__(16) int   g_rowptr[NN + 1];
__device__ __align__(16) int   g_fill[NN];
__device__ __align__(16) int   g_partial[MAX_BLK];
__device__ __align__(16) int   g_pscan[MAX_BLK];
__device__ __align__(16) int   g_adj[EDGES];
__device__ __align__(16) float g_adjw[EDGES];
__device__ __align__(16) float g_h1[(size_t)NN * HID];
__device__ __align__(16) float g_x1[(size_t)NN * HID];
__device__ __align__(16) float g_h2[(size_t)NN * OUTC];
__device__ __align__(16) float g_x2[(size_t)NN * OUTC];
__device__ __align__(16) float g_sum1[HID];
__device__ __align__(16) float g_sq1[HID];
__device__ __align__(16) float g_sum2[OUTC];
__device__ __align__(16) float g_sq2[OUTC];
__device__ __align__(16) float g_sc1[HID];
__device__ __align__(16) float g_sh1[HID];
__device__ __align__(16) float g_sc2[OUTC];
__device__ __align__(16) float g_sh2[OUTC];

// ---------------- helpers ---------------------------------------------------
__device__ __forceinline__ void red4(float* p, float4 v) {
    asm volatile("red.global.add.v4.f32 [%0], {%1, %2, %3, %4};"
                 :: "l"(p), "f"(v.x), "f"(v.y), "f"(v.z), "f"(v.w) : "memory");
}

__device__ __forceinline__ unsigned sptr(const void* p) {
    return (unsigned)__cvta_generic_to_shared(p);
}

__device__ __forceinline__ void ldsm4(unsigned* r, unsigned addr) {
    asm volatile("ldmatrix.sync.aligned.m8n8.x4.shared.b16 {%0,%1,%2,%3}, [%4];"
                 : "=r"(r[0]), "=r"(r[1]), "=r"(r[2]), "=r"(r[3]) : "r"(addr));
}

__device__ __forceinline__ void ldsm4t(unsigned* r, unsigned addr) {
    asm volatile("ldmatrix.sync.aligned.m8n8.x4.trans.shared.b16 {%0,%1,%2,%3}, [%4];"
                 : "=r"(r[0]), "=r"(r[1]), "=r"(r[2]), "=r"(r[3]) : "r"(addr));
}

__device__ __forceinline__ void mma16816(float* d, const unsigned* a, const unsigned* b) {
    asm volatile("mma.sync.aligned.m16n8k16.row.col.f32.bf16.bf16.f32 "
                 "{%0,%1,%2,%3}, {%4,%5,%6,%7}, {%8,%9}, {%0,%1,%2,%3};"
                 : "+f"(d[0]), "+f"(d[1]), "+f"(d[2]), "+f"(d[3])
                 : "r"(a[0]), "r"(a[1]), "r"(a[2]), "r"(a[3]),
                   "r"(b[0]), "r"(b[1]));
}

__device__ __forceinline__ void split_store2(float x, float y,
                                             __nv_bfloat16* hp, __nv_bfloat16* lp) {
    __nv_bfloat16 hx = __float2bfloat16_rn(x);
    __nv_bfloat16 hy = __float2bfloat16_rn(y);
    __nv_bfloat16 lx = __float2bfloat16_rn(x - __bfloat162float(hx));
    __nv_bfloat16 ly = __float2bfloat16_rn(y - __bfloat162float(hy));
    *reinterpret_cast<__nv_bfloat162*>(hp) = __halves2bfloat162(hx, hy);
    *reinterpret_cast<__nv_bfloat162*>(lp) = __halves2bfloat162(lx, ly);
}

// ---------------- CSR build -------------------------------------------------
__global__ void k_zero(int* cnt, float* sum1, float* sq1, float* sum2, float* sq2, int n) {
    int i = blockIdx.x * blockDim.x + threadIdx.x;
    if (i < n) cnt[i] = 0;
    if (i < HID)  { sum1[i] = 0.f; sq1[i] = 0.f; }
    if (i < OUTC) { sum2[i] = 0.f; sq2[i] = 0.f; }
}

__global__ void k_count(const int* __restrict__ dst, int* cnt, int E) {
    int e = blockIdx.x * blockDim.x + threadIdx.x;
    if (e < E) atomicAdd(&cnt[dst[e]], 1);
}

__global__ void k_scan1(const int* __restrict__ cnt, int* partial, int n) {
    __shared__ int sm[256];
    int t = threadIdx.x;
    int base = blockIdx.x * SCAN_CHUNK + t;
    int s = 0;
#pragma unroll
    for (int i = 0; i < 4; i++) {
        int idx = base + i * 256;
        if (idx < n) s += cnt[idx];
    }
    sm[t] = s;
    __syncthreads();
    for (int off = 128; off; off >>= 1) {
        if (t < off) sm[t] += sm[t + off];
        __syncthreads();
    }
    if (t == 0) partial[blockIdx.x] = sm[0];
}

__global__ void k_scan2(const int* __restrict__ partial, int* pscan, int* rowptr,
                        int nblk, int n) {
    if (threadIdx.x == 0) {
        int acc = 0;
        for (int b = 0; b < nblk; b++) { pscan[b] = acc; acc += partial[b]; }
        rowptr[n] = acc;
    }
}

__global__ void k_scan3(const int* __restrict__ cnt, const int* __restrict__ pscan,
                        int* rowptr, int* fill, int n) {
    __shared__ int tsum[256];
    int t = threadIdx.x;
    int base = blockIdx.x * SCAN_CHUNK + t * 4;
    int v[4];
    int local = 0;
#pragma unroll
    for (int i = 0; i < 4; i++) {
        v[i] = (base + i < n) ? cnt[base + i] : 0;
        local += v[i];
    }
    tsum[t] = local;
    __syncthreads();
    for (int off = 1; off < 256; off <<= 1) {
        int x = 0;
        if (t >= off) x = tsum[t - off];
        __syncthreads();
        if (t >= off) tsum[t] += x;
        __syncthreads();
    }
    int run = tsum[t] - local + pscan[blockIdx.x];
#pragma unroll
    for (int i = 0; i < 4; i++) {
        if (base + i < n) { rowptr[base + i] = run; fill[base + i] = run; }
        run += v[i];
    }
}

__global__ void k_dinv(const int* __restrict__ cnt, float* dinv, int n) {
    int i = blockIdx.x * blockDim.x + threadIdx.x;
    if (i < n) dinv[i] = rsqrtf((float)(cnt[i] + 1));
}

__global__ void k_fill(const int* __restrict__ src, const int* __restrict__ dst,
                       const float* __restrict__ dinv,
                       int* fill, int* adj, float* adjw, int E) {
    int e = blockIdx.x * blockDim.x + threadIdx.x;
    if (e >= E) return;
    int s = src[e], d = dst[e];
    int pos = atomicAdd(&fill[d], 1);
    adj[pos] = s;
    adjw[pos] = __ldg(dinv + s) * __ldg(dinv + d);
}

// ---------------- tensor-core GEMM (bf16 split-3), register-staged ----------
template <int BN, int FUSE, int KD>
__global__ __launch_bounds__(256, 2)
void k_gemm_tc(const float* __restrict__ A, const float* __restrict__ B,
               float* __restrict__ C, int M,
               const float* __restrict__ sc, const float* __restrict__ sh) {
    constexpr int BM = 128, BK = 32;
    constexpr int WN_EXT = BN / 2;
    constexpr int N16 = WN_EXT / 16;
    constexpr int ASTR = BK + 8;
    constexpr int BSTR = BN + 8;
    constexpr int BV = (BK * BN / 4) / 256;

    __shared__ __nv_bfloat16 Ah[BM][ASTR], Al[BM][ASTR];
    __shared__ __nv_bfloat16 Bh[BK][BSTR], Bl[BK][BSTR];
    __shared__ float ssc[FUSE ? KD : 1], ssh[FUSE ? KD : 1];

    const int tid  = threadIdx.x;
    const int lane = tid & 31;
    const int w    = tid >> 5;
    const int warp_m0 = (w >> 1) * 32;
    const int warp_n0 = (w & 1) * WN_EXT;
    const int bm0 = blockIdx.x * BM;

    if (FUSE) {
        for (int i = tid; i < KD; i += 256) { ssc[i] = sc[i]; ssh[i] = sh[i]; }
        __syncthreads();
    }

    float acc[2][N16 * 2][4];
#pragma unroll
    for (int mi = 0; mi < 2; mi++)
#pragma unroll
        for (int t = 0; t < N16 * 2; t++)
#pragma unroll
            for (int j = 0; j < 4; j++) acc[mi][t][j] = 0.f;

    const int lm_row = lane & 15;
    const int lm_off = (lane >> 4) << 3;

    float4 ra[4], rb[BV];

    // prologue: stage tile kt=0
#pragma unroll
    for (int t = 0; t < 4; t++) {
        int idx = tid + t * 256;
        int row = idx >> 3, q = idx & 7;
        int gr = bm0 + row;
        ra[t] = (gr < M) ? *reinterpret_cast<const float4*>(A + (size_t)gr * KD + q * 4)
                         : make_float4(0.f, 0.f, 0.f, 0.f);
    }
#pragma unroll
    for (int t = 0; t < BV; t++) {
        int idx = tid + t * 256;
        int row = idx / (BN / 4), q = idx % (BN / 4);
        rb[t] = *reinterpret_cast<const float4*>(B + (size_t)row * BN + q * 4);
    }

    for (int kt = 0; kt < KD; kt += BK) {
        // ---- convert staged regs -> smem (split hi/lo) ----
#pragma unroll
        for (int t = 0; t < 4; t++) {
            int idx = tid + t * 256;
            int row = idx >> 3, q = idx & 7;
            float4 v = ra[t];
            if (FUSE) {
                int kg = kt + q * 4;
                v.x = fmaxf(fmaf(v.x, ssc[kg + 0], ssh[kg + 0]), 0.f);
                v.y = fmaxf(fmaf(v.y, ssc[kg + 1], ssh[kg + 1]), 0.f);
                v.z = fmaxf(fmaf(v.z, ssc[kg + 2], ssh[kg + 2]), 0.f);
                v.w = fmaxf(fmaf(v.w, ssc[kg + 3], ssh[kg + 3]), 0.f);
            }
            split_store2(v.x, v.y, &Ah[row][q * 4],     &Al[row][q * 4]);
            split_store2(v.z, v.w, &Ah[row][q * 4 + 2], &Al[row][q * 4 + 2]);
        }
#pragma unroll
        for (int t = 0; t < BV; t++) {
            int idx = tid + t * 256;
            int row = idx / (BN / 4), q = idx % (BN / 4);
            float4 v = rb[t];
            split_store2(v.x, v.y, &Bh[row][q * 4],     &Bl[row][q * 4]);
            split_store2(v.z, v.w, &Bh[row][q * 4 + 2], &Bl[row][q * 4 + 2]);
        }
        __syncthreads();

        // ---- stage next tile (overlaps with MMA below) ----
        if (kt + BK < KD) {
            int kn = kt + BK;
#pragma unroll
            for (int t = 0; t < 4; t++) {
                int idx = tid + t * 256;
                int row = idx >> 3, q = idx & 7;
                int gr = bm0 + row;
                ra[t] = (gr < M) ? *reinterpret_cast<const float4*>(A + (size_t)gr * KD + kn + q * 4)
                                 : make_float4(0.f, 0.f, 0.f, 0.f);
            }
#pragma unroll
            for (int t = 0; t < BV; t++) {
                int idx = tid + t * 256;
                int row = idx / (BN / 4), q = idx % (BN / 4);
                rb[t] = *reinterpret_cast<const float4*>(B + (size_t)(kn + row) * BN + q * 4);
            }
        }

        // ---- MMA over two k16 steps ----
#pragma unroll
        for (int ks = 0; ks < BK; ks += 16) {
            unsigned ah[2][4], al[2][4];
#pragma unroll
            for (int mi = 0; mi < 2; mi++) {
                int r = warp_m0 + mi * 16 + lm_row;
                int c = ks + lm_off;
                ldsm4(ah[mi], sptr(&Ah[r][c]));
                ldsm4(al[mi], sptr(&Al[r][c]));
            }
#pragma unroll
            for (int ng = 0; ng < N16; ng++) {
                unsigned bh[4], bl[4];
                int br = ks + lm_row;
                int bc = warp_n0 + ng * 16 + lm_off;
                ldsm4t(bh, sptr(&Bh[br][bc]));
                ldsm4t(bl, sptr(&Bl[br][bc]));
#pragma unroll
                for (int mi = 0; mi < 2; mi++) {
#pragma unroll
                    for (int h = 0; h < 2; h++) {
                        float* d = acc[mi][ng * 2 + h];
                        mma16816(d, ah[mi], &bh[h * 2]);
                        mma16816(d, ah[mi], &bl[h * 2]);
                        mma16816(d, al[mi], &bh[h * 2]);
                    }
                }
            }
        }
        __syncthreads();
    }

    // ---- epilogue ----
#pragma unroll
    for (int mi = 0; mi < 2; mi++) {
        int r0 = bm0 + warp_m0 + mi * 16 + (lane >> 2);
#pragma unroll
        for (int t = 0; t < N16 * 2; t++) {
            int c = warp_n0 + t * 8 + (lane & 3) * 2;
            if (r0 < M)
                *reinterpret_cast<float2*>(C + (size_t)r0 * BN + c) =
                    make_float2(acc[mi][t][0], acc[mi][t][1]);
            if (r0 + 8 < M)
                *reinterpret_cast<float2*>(C + (size_t)(r0 + 8) * BN + c) =
                    make_float2(acc[mi][t][2], acc[mi][t][3]);
        }
    }
}

// ------------- CSR pull aggregation: selfloop+bias + gather + BN stats ------
template <int C>
__global__ __launch_bounds__(256)
void k_aggr(const int* __restrict__ rowptr, const int* __restrict__ adj,
            const float* __restrict__ adjw,
            const float* __restrict__ h, const float* __restrict__ dinv,
            const float* __restrict__ bias, float* __restrict__ x,
            float* __restrict__ sum, float* __restrict__ sq, int n) {
    constexpr int L = C / 4;                      // lanes per node group
    __shared__ float bs[C], bq[C];
    int tid = threadIdx.x;
    if (tid < C) { bs[tid] = 0.f; bq[tid] = 0.f; }
    __syncthreads();

    const int lpos = tid % L;
    const int gid = (blockIdx.x * blockDim.x + tid) / L;
    const int stride = (gridDim.x * blockDim.x) / L;
    const float4 bv = *reinterpret_cast<const float4*>(bias + lpos * 4);

    float s0 = 0.f, s1 = 0.f, s2 = 0.f, s3 = 0.f;
    float q0 = 0.f, q1 = 0.f, q2 = 0.f, q3 = 0.f;

    for (int node = gid; node < n; node += stride) {
        float dd = __ldg(dinv + node);
        float4 hv = *reinterpret_cast<const float4*>(h + (size_t)node * C + lpos * 4);
        float nn = dd * dd;
        float4 acc = make_float4(fmaf(hv.x, nn, bv.x), fmaf(hv.y, nn, bv.y),
                                 fmaf(hv.z, nn, bv.z), fmaf(hv.w, nn, bv.w));
        int beg = __ldg(rowptr + node);
        int end = __ldg(rowptr + node + 1);
        int j = beg;
        for (; j + 2 <= end; j += 2) {
            int i0 = __ldg(adj + j), i1 = __ldg(adj + j + 1);
            float w0 = __ldg(adjw + j), w1 = __ldg(adjw + j + 1);
            float4 v0 = *reinterpret_cast<const float4*>(h + (size_t)i0 * C + lpos * 4);
            float4 v1 = *reinterpret_cast<const float4*>(h + (size_t)i1 * C + lpos * 4);
            acc.x = fmaf(v0.x, w0, acc.x); acc.y = fmaf(v0.y, w0, acc.y);
            acc.z = fmaf(v0.z, w0, acc.z); acc.w = fmaf(v0.w, w0, acc.w);
            acc.x = fmaf(v1.x, w1, acc.x); acc.y = fmaf(v1.y, w1, acc.y);
            acc.z = fmaf(v1.z, w1, acc.z); acc.w = fmaf(v1.w, w1, acc.w);
        }
        if (j < end) {
            int i0 = __ldg(adj + j);
            float w0 = __ldg(adjw + j);
            float4 v0 = *reinterpret_cast<const float4*>(h + (size_t)i0 * C + lpos * 4);
            acc.x = fmaf(v0.x, w0, acc.x); acc.y = fmaf(v0.y, w0, acc.y);
            acc.z = fmaf(v0.z, w0, acc.z); acc.w = fmaf(v0.w, w0, acc.w);
        }
        *reinterpret_cast<float4*>(x + (size_t)node * C + lpos * 4) = acc;
        s0 += acc.x; s1 += acc.y; s2 += acc.z; s3 += acc.w;
        q0 += acc.x * acc.x; q1 += acc.y * acc.y;
        q2 += acc.z * acc.z; q3 += acc.w * acc.w;
    }

    atomicAdd(&bs[lpos * 4 + 0], s0); atomicAdd(&bs[lpos * 4 + 1], s1);
    atomicAdd(&bs[lpos * 4 + 2], s2); atomicAdd(&bs[lpos * 4 + 3], s3);
    atomicAdd(&bq[lpos * 4 + 0], q0); atomicAdd(&bq[lpos * 4 + 1], q1);
    atomicAdd(&bq[lpos * 4 + 2], q2); atomicAdd(&bq[lpos * 4 + 3], q3);
    __syncthreads();
    if (tid < C / 4) {
        red4(&sum[tid * 4], make_float4(bs[tid * 4], bs[tid * 4 + 1], bs[tid * 4 + 2], bs[tid * 4 + 3]));
        red4(&sq[tid * 4],  make_float4(bq[tid * 4], bq[tid * 4 + 1], bq[tid * 4 + 2], bq[tid * 4 + 3]));
    }
}

// ---------------- BN finalize ------------------------------------------------
__global__ void k_bnfin(const float* __restrict__ sum, const float* __restrict__ sq,
                        const float* __restrict__ gamma, const float* __restrict__ beta,
                        float* __restrict__ sc, float* __restrict__ sh, int C, float invN) {
    int c = threadIdx.x;
    if (c >= C) return;
    float mu = sum[c] * invN;
    float var = sq[c] * invN - mu * mu;
    float s = gamma[c] * rsqrtf(var + 1e-5f);
    sc[c] = s;
    sh[c] = fmaf(-mu, s, beta[c]);
}

// ---------------- gather + BN2 + ReLU + log_softmax -------------------------
__global__ void k_out(const float* __restrict__ x2, const int* __restrict__ batch,
                      const float* __restrict__ sc, const float* __restrict__ sh,
                      float* __restrict__ out, int NB) {
    int warp = (blockIdx.x * blockDim.x + threadIdx.x) >> 5;
    if (warp >= NB) return;
    int lane = threadIdx.x & 31;
    int node = __ldg(batch + warp);
    float v0 = fmaxf(fmaf(x2[(size_t)node * OUTC + lane], sc[lane], sh[lane]), 0.f);
    float v1 = fmaxf(fmaf(x2[(size_t)node * OUTC + lane + 32], sc[lane + 32], sh[lane + 32]), 0.f);
    float m = fmaxf(v0, v1);
#pragma unroll
    for (int o = 16; o; o >>= 1) m = fmaxf(m, __shfl_xor_sync(0xffffffffu, m, o));
    float s = expf(v0 - m) + expf(v1 - m);
#pragma unroll
    for (int o = 16; o; o >>= 1) s += __shfl_xor_sync(0xffffffffu, s, o);
    float lse = m + logf(s);
    out[(size_t)warp * OUTC + lane] = v0 - lse;
    out[(size_t)warp * OUTC + lane + 32] = v1 - lse;
}

// ---------------- launch ----------------------------------------------------
extern "C" void kernel_launch(void* const* d_in, const int* in_sizes, int n_in,
                              void* d_out, int out_size) {
    const float* features = (const float*)d_in[0];
    const int*   edge     = (const int*)d_in[1];
    const int*   batch    = (const int*)d_in[2];
    const float* W1 = (const float*)d_in[3];
    const float* b1 = (const float*)d_in[4];
    const float* gamma1 = (const float*)d_in[5];
    const float* beta1  = (const float*)d_in[6];
    const float* W2 = (const float*)d_in[7];
    const float* b2 = (const float*)d_in[8];
    const float* gamma2 = (const float*)d_in[9];
    const float* beta2  = (const float*)d_in[10];
    float* out = (float*)d_out;

    const int n  = in_sizes[0] / FEAT;
    const int E  = in_sizes[1] / 2;
    const int NB = in_sizes[2];
    const int* src = edge;
    const int* dst = edge + E;

    float *p_dinv, *p_h1, *p_x1, *p_h2, *p_x2;
    float *p_sum1, *p_sq1, *p_sum2, *p_sq2, *p_sc1, *p_sh1, *p_sc2, *p_sh2;
    float *p_adjw;
    int *p_cnt, *p_rowptr, *p_fill, *p_partial, *p_pscan, *p_adj;
    cudaGetSymbolAddress((void**)&p_dinv, g_dinv);
    cudaGetSymbolAddress((void**)&p_cnt, g_cnt);
    cudaGetSymbolAddress((void**)&p_rowptr, g_rowptr);
    cudaGetSymbolAddress((void**)&p_fill, g_fill);
    cudaGetSymbolAddress((void**)&p_partial, g_partial);
    cudaGetSymbolAddress((void**)&p_pscan, g_pscan);
    cudaGetSymbolAddress((void**)&p_adj, g_adj);
    cudaGetSymbolAddress((void**)&p_adjw, g_adjw);
    cudaGetSymbolAddress((void**)&p_h1, g_h1);
    cudaGetSymbolAddress((void**)&p_x1, g_x1);
    cudaGetSymbolAddress((void**)&p_h2, g_h2);
    cudaGetSymbolAddress((void**)&p_x2, g_x2);
    cudaGetSymbolAddress((void**)&p_sum1, g_sum1);
    cudaGetSymbolAddress((void**)&p_sq1, g_sq1);
    cudaGetSymbolAddress((void**)&p_sum2, g_sum2);
    cudaGetSymbolAddress((void**)&p_sq2, g_sq2);
    cudaGetSymbolAddress((void**)&p_sc1, g_sc1);
    cudaGetSymbolAddress((void**)&p_sh1, g_sh1);
    cudaGetSymbolAddress((void**)&p_sc2, g_sc2);
    cudaGetSymbolAddress((void**)&p_sh2, g_sh2);

    const float invN = 1.0f / (float)n;
    const int nblk = (n + SCAN_CHUNK - 1) / SCAN_CHUNK;

    // ---- CSR build ----
    k_zero<<<(n + 255) / 256, 256>>>(p_cnt, p_sum1, p_sq1, p_sum2, p_sq2, n);
    k_count<<<(E + 255) / 256, 256>>>(dst, p_cnt, E);
    k_scan1<<<nblk, 256>>>(p_cnt, p_partial, n);
    k_scan2<<<1, 32>>>(p_partial, p_pscan, p_rowptr, nblk, n);
    k_scan3<<<nblk, 256>>>(p_cnt, p_pscan, p_rowptr, p_fill, n);
    k_dinv<<<(n + 255) / 256, 256>>>(p_cnt, p_dinv, n);
    k_fill<<<(E + 255) / 256, 256>>>(src, dst, p_dinv, p_fill, p_adj, p_adjw, E);

    // ---- layer 1 ----
    k_gemm_tc<HID, 0, FEAT><<<(n + 127) / 128, 256>>>(
        features, W1, p_h1, n, nullptr, nullptr);
    k_aggr<HID><<<1184, 256>>>(p_rowptr, p_adj, p_adjw, p_h1, p_dinv, b1,
                               p_x1, p_sum1, p_sq1, n);
    k_bnfin<<<1, 128>>>(p_sum1, p_sq1, gamma1, beta1, p_sc1, p_sh1, HID, invN);

    // ---- layer 2 (BN1+ReLU fused into GEMM A conversion) ----
    k_gemm_tc<OUTC, 1, HID><<<(n + 127) / 128, 256>>>(
        p_x1, W2, p_h2, n, p_sc1, p_sh1);
    k_aggr<OUTC><<<1184, 256>>>(p_rowptr, p_adj, p_adjw, p_h2, p_dinv, b2,
                                p_x2, p_sum2, p_sq2, n);
    k_bnfin<<<1, 64>>>(p_sum2, p_sq2, gamma2, beta2, p_sc2, p_sh2, OUTC, invN);

    // ---- output ----
    k_out<<<(NB * 32 + 255) / 256, 256>>>(p_x2, batch, p_sc2, p_sh2, out, NB);
}

// round 17
// speedup vs baseline: 1.0449x; 1.0449x over previous
#include <cuda_runtime.h>
#include <cuda_bf16.h>
#include <cuda_fp16.h>
#include <math.h>

#define NN 100000
#define EDGES 1600000
#define FEAT 256
#define HID 128
#define OUTC 64
#define SCAN_CHUNK 1024
#define MAX_BLK ((NN + SCAN_CHUNK - 1) / SCAN_CHUNK + 1)

// ---------------- scratch (device globals; no allocation allowed) ----------
__device__ __align__(16) float g_dinv[NN];
__device__ __align__(16) int   g_cnt[NN];
__device__ __align__(16) int   g_rowptr[NN + 1];
__device__ __align__(16) int   g_fill[NN];
__device__ __align__(16) int   g_partial[MAX_BLK];
__device__ __align__(16) int   g_pscan[MAX_BLK];
__device__ __align__(16) int2  g_adjp[EDGES];          // (src, weight bits)
__device__ __align__(16) __half g_h1[(size_t)NN * HID];
__device__ __align__(16) float  g_x1[(size_t)NN * HID];
__device__ __align__(16) __half g_h2[(size_t)NN * OUTC];
__device__ __align__(16) float  g_x2[(size_t)NN * OUTC];
__device__ __align__(16) float g_sum1[HID];
__device__ __align__(16) float g_sq1[HID];
__device__ __align__(16) float g_sum2[OUTC];
__device__ __align__(16) float g_sq2[OUTC];
__device__ __align__(16) float g_sc1[HID];
__device__ __align__(16) float g_sh1[HID];
__device__ __align__(16) float g_sc2[OUTC];
__device__ __align__(16) float g_sh2[OUTC];

// ---------------- helpers ---------------------------------------------------
__device__ __forceinline__ void red4(float* p, float4 v) {
    asm volatile("red.global.add.v4.f32 [%0], {%1, %2, %3, %4};"
                 :: "l"(p), "f"(v.x), "f"(v.y), "f"(v.z), "f"(v.w) : "memory");
}

__device__ __forceinline__ unsigned sptr(const void* p) {
    return (unsigned)__cvta_generic_to_shared(p);
}

__device__ __forceinline__ void ldsm4(unsigned* r, unsigned addr) {
    asm volatile("ldmatrix.sync.aligned.m8n8.x4.shared.b16 {%0,%1,%2,%3}, [%4];"
                 : "=r"(r[0]), "=r"(r[1]), "=r"(r[2]), "=r"(r[3]) : "r"(addr));
}

__device__ __forceinline__ void ldsm4t(unsigned* r, unsigned addr) {
    asm volatile("ldmatrix.sync.aligned.m8n8.x4.trans.shared.b16 {%0,%1,%2,%3}, [%4];"
                 : "=r"(r[0]), "=r"(r[1]), "=r"(r[2]), "=r"(r[3]) : "r"(addr));
}

__device__ __forceinline__ void mma16816(float* d, const unsigned* a, const unsigned* b) {
    asm volatile("mma.sync.aligned.m16n8k16.row.col.f32.bf16.bf16.f32 "
                 "{%0,%1,%2,%3}, {%4,%5,%6,%7}, {%8,%9}, {%0,%1,%2,%3};"
                 : "+f"(d[0]), "+f"(d[1]), "+f"(d[2]), "+f"(d[3])
                 : "r"(a[0]), "r"(a[1]), "r"(a[2]), "r"(a[3]),
                   "r"(b[0]), "r"(b[1]));
}

__device__ __forceinline__ void split_store2(float x, float y,
                                             __nv_bfloat16* hp, __nv_bfloat16* lp) {
    __nv_bfloat16 hx = __float2bfloat16_rn(x);
    __nv_bfloat16 hy = __float2bfloat16_rn(y);
    __nv_bfloat16 lx = __float2bfloat16_rn(x - __bfloat162float(hx));
    __nv_bfloat16 ly = __float2bfloat16_rn(y - __bfloat162float(hy));
    *reinterpret_cast<__nv_bfloat162*>(hp) = __halves2bfloat162(hx, hy);
    *reinterpret_cast<__nv_bfloat162*>(lp) = __halves2bfloat162(lx, ly);
}

__device__ __forceinline__ void fma8(float* acc, uint4 v, float w) {
    __half2 h0 = *reinterpret_cast<__half2*>(&v.x);
    __half2 h1 = *reinterpret_cast<__half2*>(&v.y);
    __half2 h2 = *reinterpret_cast<__half2*>(&v.z);
    __half2 h3 = *reinterpret_cast<__half2*>(&v.w);
    float2 f0 = __half22float2(h0), f1 = __half22float2(h1);
    float2 f2 = __half22float2(h2), f3 = __half22float2(h3);
    acc[0] = fmaf(f0.x, w, acc[0]); acc[1] = fmaf(f0.y, w, acc[1]);
    acc[2] = fmaf(f1.x, w, acc[2]); acc[3] = fmaf(f1.y, w, acc[3]);
    acc[4] = fmaf(f2.x, w, acc[4]); acc[5] = fmaf(f2.y, w, acc[5]);
    acc[6] = fmaf(f3.x, w, acc[6]); acc[7] = fmaf(f3.y, w, acc[7]);
}

// ---------------- CSR build -------------------------------------------------
__global__ void k_zero(int* cnt, float* sum1, float* sq1, float* sum2, float* sq2, int n) {
    int i = blockIdx.x * blockDim.x + threadIdx.x;
    if (i < n) cnt[i] = 0;
    if (i < HID)  { sum1[i] = 0.f; sq1[i] = 0.f; }
    if (i < OUTC) { sum2[i] = 0.f; sq2[i] = 0.f; }
}

__global__ void k_count(const int* __restrict__ dst, int* cnt, int E) {
    int e = blockIdx.x * blockDim.x + threadIdx.x;
    if (e < E) atomicAdd(&cnt[dst[e]], 1);
}

__global__ void k_scan1(const int* __restrict__ cnt, int* partial, int n) {
    __shared__ int sm[256];
    int t = threadIdx.x;
    int base = blockIdx.x * SCAN_CHUNK + t;
    int s = 0;
#pragma unroll
    for (int i = 0; i < 4; i++) {
        int idx = base + i * 256;
        if (idx < n) s += cnt[idx];
    }
    sm[t] = s;
    __syncthreads();
    for (int off = 128; off; off >>= 1) {
        if (t < off) sm[t] += sm[t + off];
        __syncthreads();
    }
    if (t == 0) partial[blockIdx.x] = sm[0];
}

// parallel exclusive scan of per-block partials (nblk <= 128 fast path)
__global__ void k_scan2(const int* __restrict__ partial, int* pscan, int* rowptr,
                        int nblk, int n) {
    int t = threadIdx.x;                          // 128 threads
    if (nblk <= 128) {
        int v = (t < nblk) ? partial[t] : 0;
        int x = v;
#pragma unroll
        for (int o = 1; o < 32; o <<= 1) {
            int y = __shfl_up_sync(0xffffffffu, x, o);
            if ((t & 31) >= o) x += y;
        }
        __shared__ int wsum[4];
        if ((t & 31) == 31) wsum[t >> 5] = x;
        __syncthreads();
        if (t < 4) {
            int y = wsum[t];
#pragma unroll
            for (int o = 1; o < 4; o <<= 1) {
                int z = __shfl_up_sync(0xfu, y, o);
                if (t >= o) y += z;
            }
            wsum[t] = y;
        }
        __syncthreads();
        int incl = x + ((t >= 32) ? wsum[(t >> 5) - 1] : 0);
        if (t < nblk) pscan[t] = incl - v;
        if (t == 127) rowptr[n] = incl;
    } else if (t == 0) {
        int acc = 0;
        for (int b = 0; b < nblk; b++) { pscan[b] = acc; acc += partial[b]; }
        rowptr[n] = acc;
    }
}

__global__ void k_scan3(const int* __restrict__ cnt, const int* __restrict__ pscan,
                        int* rowptr, int* fill, float* dinv, int n) {
    __shared__ int tsum[256];
    int t = threadIdx.x;
    int base = blockIdx.x * SCAN_CHUNK + t * 4;
    int v[4];
    int local = 0;
#pragma unroll
    for (int i = 0; i < 4; i++) {
        v[i] = (base + i < n) ? cnt[base + i] : 0;
        local += v[i];
    }
    tsum[t] = local;
    __syncthreads();
    for (int off = 1; off < 256; off <<= 1) {
        int x = 0;
        if (t >= off) x = tsum[t - off];
        __syncthreads();
        if (t >= off) tsum[t] += x;
        __syncthreads();
    }
    int run = tsum[t] - local + pscan[blockIdx.x];
#pragma unroll
    for (int i = 0; i < 4; i++) {
        if (base + i < n) {
            rowptr[base + i] = run;
            fill[base + i] = run;
            dinv[base + i] = rsqrtf((float)(v[i] + 1));
        }
        run += v[i];
    }
}

__global__ void k_fill(const int* __restrict__ src, const int* __restrict__ dst,
                       const float* __restrict__ dinv,
                       int* fill, int2* adjp, int E) {
    int e = blockIdx.x * blockDim.x + threadIdx.x;
    if (e >= E) return;
    int s = src[e], d = dst[e];
    int pos = atomicAdd(&fill[d], 1);
    float w = __ldg(dinv + s) * __ldg(dinv + d);
    adjp[pos] = make_int2(s, __float_as_int(w));
}

// ---------------- tensor-core GEMM (bf16 split-3), fp16 output --------------
template <int BN, int FUSE, int KD>
__global__ __launch_bounds__(256, 2)
void k_gemm_tc(const float* __restrict__ A, const float* __restrict__ B,
               __half* __restrict__ C, int M,
               const float* __restrict__ sc, const float* __restrict__ sh) {
    constexpr int BM = 128, BK = 32;
    constexpr int WN_EXT = BN / 2;
    constexpr int N16 = WN_EXT / 16;
    constexpr int ASTR = BK + 8;
    constexpr int BSTR = BN + 8;
    constexpr int BV = (BK * BN / 4) / 256;

    __shared__ __nv_bfloat16 Ah[BM][ASTR], Al[BM][ASTR];
    __shared__ __nv_bfloat16 Bh[BK][BSTR], Bl[BK][BSTR];
    __shared__ float ssc[FUSE ? KD : 1], ssh[FUSE ? KD : 1];

    const int tid  = threadIdx.x;
    const int lane = tid & 31;
    const int w    = tid >> 5;
    const int warp_m0 = (w >> 1) * 32;
    const int warp_n0 = (w & 1) * WN_EXT;
    const int bm0 = blockIdx.x * BM;

    if (FUSE) {
        for (int i = tid; i < KD; i += 256) { ssc[i] = sc[i]; ssh[i] = sh[i]; }
        __syncthreads();
    }

    float acc[2][N16 * 2][4];
#pragma unroll
    for (int mi = 0; mi < 2; mi++)
#pragma unroll
        for (int t = 0; t < N16 * 2; t++)
#pragma unroll
            for (int j = 0; j < 4; j++) acc[mi][t][j] = 0.f;

    const int lm_row = lane & 15;
    const int lm_off = (lane >> 4) << 3;

    float4 ra[4], rb[BV];

#pragma unroll
    for (int t = 0; t < 4; t++) {
        int idx = tid + t * 256;
        int row = idx >> 3, q = idx & 7;
        int gr = bm0 + row;
        ra[t] = (gr < M) ? *reinterpret_cast<const float4*>(A + (size_t)gr * KD + q * 4)
                         : make_float4(0.f, 0.f, 0.f, 0.f);
    }
#pragma unroll
    for (int t = 0; t < BV; t++) {
        int idx = tid + t * 256;
        int row = idx / (BN / 4), q = idx % (BN / 4);
        rb[t] = *reinterpret_cast<const float4*>(B + (size_t)row * BN + q * 4);
    }

    for (int kt = 0; kt < KD; kt += BK) {
#pragma unroll
        for (int t = 0; t < 4; t++) {
            int idx = tid + t * 256;
            int row = idx >> 3, q = idx & 7;
            float4 v = ra[t];
            if (FUSE) {
                int kg = kt + q * 4;
                v.x = fmaxf(fmaf(v.x, ssc[kg + 0], ssh[kg + 0]), 0.f);
                v.y = fmaxf(fmaf(v.y, ssc[kg + 1], ssh[kg + 1]), 0.f);
                v.z = fmaxf(fmaf(v.z, ssc[kg + 2], ssh[kg + 2]), 0.f);
                v.w = fmaxf(fmaf(v.w, ssc[kg + 3], ssh[kg + 3]), 0.f);
            }
            split_store2(v.x, v.y, &Ah[row][q * 4],     &Al[row][q * 4]);
            split_store2(v.z, v.w, &Ah[row][q * 4 + 2], &Al[row][q * 4 + 2]);
        }
#pragma unroll
        for (int t = 0; t < BV; t++) {
            int idx = tid + t * 256;
            int row = idx / (BN / 4), q = idx % (BN / 4);
            float4 v = rb[t];
            split_store2(v.x, v.y, &Bh[row][q * 4],     &Bl[row][q * 4]);
            split_store2(v.z, v.w, &Bh[row][q * 4 + 2], &Bl[row][q * 4 + 2]);
        }
        __syncthreads();

        if (kt + BK < KD) {
            int kn = kt + BK;
#pragma unroll
            for (int t = 0; t < 4; t++) {
                int idx = tid + t * 256;
                int row = idx >> 3, q = idx & 7;
                int gr = bm0 + row;
                ra[t] = (gr < M) ? *reinterpret_cast<const float4*>(A + (size_t)gr * KD + kn + q * 4)
                                 : make_float4(0.f, 0.f, 0.f, 0.f);
            }
#pragma unroll
            for (int t = 0; t < BV; t++) {
                int idx = tid + t * 256;
                int row = idx / (BN / 4), q = idx % (BN / 4);
                rb[t] = *reinterpret_cast<const float4*>(B + (size_t)(kn + row) * BN + q * 4);
            }
        }

#pragma unroll
        for (int ks = 0; ks < BK; ks += 16) {
            unsigned ah[2][4], al[2][4];
#pragma unroll
            for (int mi = 0; mi < 2; mi++) {
                int r = warp_m0 + mi * 16 + lm_row;
                int c = ks + lm_off;
                ldsm4(ah[mi], sptr(&Ah[r][c]));
                ldsm4(al[mi], sptr(&Al[r][c]));
            }
#pragma unroll
            for (int ng = 0; ng < N16; ng++) {
                unsigned bh[4], bl[4];
                int br = ks + lm_row;
                int bc = warp_n0 + ng * 16 + lm_off;
                ldsm4t(bh, sptr(&Bh[br][bc]));
                ldsm4t(bl, sptr(&Bl[br][bc]));
#pragma unroll
                for (int mi = 0; mi < 2; mi++) {
#pragma unroll
                    for (int h = 0; h < 2; h++) {
                        float* d = acc[mi][ng * 2 + h];
                        mma16816(d, ah[mi], &bh[h * 2]);
                        mma16816(d, ah[mi], &bl[h * 2]);
                        mma16816(d, al[mi], &bh[h * 2]);
                    }
                }
            }
        }
        __syncthreads();
    }

    // ---- epilogue: fp16 store ----
#pragma unroll
    for (int mi = 0; mi < 2; mi++) {
        int r0 = bm0 + warp_m0 + mi * 16 + (lane >> 2);
#pragma unroll
        for (int t = 0; t < N16 * 2; t++) {
            int c = warp_n0 + t * 8 + (lane & 3) * 2;
            if (r0 < M)
                *reinterpret_cast<__half2*>(C + (size_t)r0 * BN + c) =
                    __floats2half2_rn(acc[mi][t][0], acc[mi][t][1]);
            if (r0 + 8 < M)
                *reinterpret_cast<__half2*>(C + (size_t)(r0 + 8) * BN + c) =
                    __floats2half2_rn(acc[mi][t][2], acc[mi][t][3]);
        }
    }
}

// ------------- CSR pull aggregation (fp16 h): selfloop+bias + BN stats ------
template <int C>
__global__ __launch_bounds__(256)
void k_aggr(const int* __restrict__ rowptr, const int2* __restrict__ adjp,
            const __half* __restrict__ h, const float* __restrict__ dinv,
            const float* __restrict__ bias, float* __restrict__ x,
            float* __restrict__ sum, float* __restrict__ sq, int n) {
    constexpr int L = C / 8;                      // lanes per node group
    __shared__ float bs[C], bq[C];
    int tid = threadIdx.x;
    if (tid < C) { bs[tid] = 0.f; bq[tid] = 0.f; }
    __syncthreads();

    const int lpos = tid % L;
    const int gid = (blockIdx.x * blockDim.x + tid) / L;
    const int stride = (gridDim.x * blockDim.x) / L;

    float bv[8];
    {
        float4 b0 = *reinterpret_cast<const float4*>(bias + lpos * 8);
        float4 b1 = *reinterpret_cast<const float4*>(bias + lpos * 8 + 4);
        bv[0] = b0.x; bv[1] = b0.y; bv[2] = b0.z; bv[3] = b0.w;
        bv[4] = b1.x; bv[5] = b1.y; bv[6] = b1.z; bv[7] = b1.w;
    }

    float s[8], q[8];
#pragma unroll
    for (int k = 0; k < 8; k++) { s[k] = 0.f; q[k] = 0.f; }

    for (int node = gid; node < n; node += stride) {
        float dd = __ldg(dinv + node);
        float nn = dd * dd;
        float acc[8];
#pragma unroll
        for (int k = 0; k < 8; k++) acc[k] = bv[k];
        uint4 hv = *reinterpret_cast<const uint4*>(h + (size_t)node * C + lpos * 8);
        fma8(acc, hv, nn);

        int beg = __ldg(rowptr + node);
        int end = __ldg(rowptr + node + 1);
        int j = beg;
        for (; j + 2 <= end; j += 2) {
            int2 a0 = __ldg(adjp + j);
            int2 a1 = __ldg(adjp + j + 1);
            uint4 v0 = *reinterpret_cast<const uint4*>(h + (size_t)a0.x * C + lpos * 8);
            uint4 v1 = *reinterpret_cast<const uint4*>(h + (size_t)a1.x * C + lpos * 8);
            fma8(acc, v0, __int_as_float(a0.y));
            fma8(acc, v1, __int_as_float(a1.y));
        }
        if (j < end) {
            int2 a0 = __ldg(adjp + j);
            uint4 v0 = *reinterpret_cast<const uint4*>(h + (size_t)a0.x * C + lpos * 8);
            fma8(acc, v0, __int_as_float(a0.y));
        }

        *reinterpret_cast<float4*>(x + (size_t)node * C + lpos * 8) =
            make_float4(acc[0], acc[1], acc[2], acc[3]);
        *reinterpret_cast<float4*>(x + (size_t)node * C + lpos * 8 + 4) =
            make_float4(acc[4], acc[5], acc[6], acc[7]);
#pragma unroll
        for (int k = 0; k < 8; k++) { s[k] += acc[k]; q[k] += acc[k] * acc[k]; }
    }

#pragma unroll
    for (int k = 0; k < 8; k++) {
        atomicAdd(&bs[lpos * 8 + k], s[k]);
        atomicAdd(&bq[lpos * 8 + k], q[k]);
    }
    __syncthreads();
    if (tid < C / 4) {
        red4(&sum[tid * 4], make_float4(bs[tid * 4], bs[tid * 4 + 1], bs[tid * 4 + 2], bs[tid * 4 + 3]));
        red4(&sq[tid * 4],  make_float4(bq[tid * 4], bq[tid * 4 + 1], bq[tid * 4 + 2], bq[tid * 4 + 3]));
    }
}

// ---------------- BN finalize ------------------------------------------------
__global__ void k_bnfin(const float* __restrict__ sum, const float* __restrict__ sq,
                        const float* __restrict__ gamma, const float* __restrict__ beta,
                        float* __restrict__ sc, float* __restrict__ sh, int C, float invN) {
    int c = threadIdx.x;
    if (c >= C) return;
    float mu = sum[c] * invN;
    float var = sq[c] * invN - mu * mu;
    float s = gamma[c] * rsqrtf(var + 1e-5f);
    sc[c] = s;
    sh[c] = fmaf(-mu, s, beta[c]);
}

// ---------------- gather + BN2 + ReLU + log_softmax -------------------------
__global__ void k_out(const float* __restrict__ x2, const int* __restrict__ batch,
                      const float* __restrict__ sc, const float* __restrict__ sh,
                      float* __restrict__ out, int NB) {
    int warp = (blockIdx.x * blockDim.x + threadIdx.x) >> 5;
    if (warp >= NB) return;
    int lane = threadIdx.x & 31;
    int node = __ldg(batch + warp);
    float v0 = fmaxf(fmaf(x2[(size_t)node * OUTC + lane], sc[lane], sh[lane]), 0.f);
    float v1 = fmaxf(fmaf(x2[(size_t)node * OUTC + lane + 32], sc[lane + 32], sh[lane + 32]), 0.f);
    float m = fmaxf(v0, v1);
#pragma unroll
    for (int o = 16; o; o >>= 1) m = fmaxf(m, __shfl_xor_sync(0xffffffffu, m, o));
    float s = expf(v0 - m) + expf(v1 - m);
#pragma unroll
    for (int o = 16; o; o >>= 1) s += __shfl_xor_sync(0xffffffffu, s, o);
    float lse = m + logf(s);
    out[(size_t)warp * OUTC + lane] = v0 - lse;
    out[(size_t)warp * OUTC + lane + 32] = v1 - lse;
}

// ---------------- launch ----------------------------------------------------
extern "C" void kernel_launch(void* const* d_in, const int* in_sizes, int n_in,
                              void* d_out, int out_size) {
    const float* features = (const float*)d_in[0];
    const int*   edge     = (const int*)d_in[1];
    const int*   batch    = (const int*)d_in[2];
    const float* W1 = (const float*)d_in[3];
    const float* b1 = (const float*)d_in[4];
    const float* gamma1 = (const float*)d_in[5];
    const float* beta1  = (const float*)d_in[6];
    const float* W2 = (const float*)d_in[7];
    const float* b2 = (const float*)d_in[8];
    const float* gamma2 = (const float*)d_in[9];
    const float* beta2  = (const float*)d_in[10];
    float* out = (float*)d_out;

    const int n  = in_sizes[0] / FEAT;
    const int E  = in_sizes[1] / 2;
    const int NB = in_sizes[2];
    const int* src = edge;
    const int* dst = edge + E;

    float *p_dinv, *p_x1, *p_x2;
    __half *p_h1, *p_h2;
    float *p_sum1, *p_sq1, *p_sum2, *p_sq2, *p_sc1, *p_sh1, *p_sc2, *p_sh2;
    int *p_cnt, *p_rowptr, *p_fill, *p_partial, *p_pscan;
    int2 *p_adjp;
    cudaGetSymbolAddress((void**)&p_dinv, g_dinv);
    cudaGetSymbolAddress((void**)&p_cnt, g_cnt);
    cudaGetSymbolAddress((void**)&p_rowptr, g_rowptr);
    cudaGetSymbolAddress((void**)&p_fill, g_fill);
    cudaGetSymbolAddress((void**)&p_partial, g_partial);
    cudaGetSymbolAddress((void**)&p_pscan, g_pscan);
    cudaGetSymbolAddress((void**)&p_adjp, g_adjp);
    cudaGetSymbolAddress((void**)&p_h1, g_h1);
    cudaGetSymbolAddress((void**)&p_x1, g_x1);
    cudaGetSymbolAddress((void**)&p_h2, g_h2);
    cudaGetSymbolAddress((void**)&p_x2, g_x2);
    cudaGetSymbolAddress((void**)&p_sum1, g_sum1);
    cudaGetSymbolAddress((void**)&p_sq1, g_sq1);
    cudaGetSymbolAddress((void**)&p_sum2, g_sum2);
    cudaGetSymbolAddress((void**)&p_sq2, g_sq2);
    cudaGetSymbolAddress((void**)&p_sc1, g_sc1);
    cudaGetSymbolAddress((void**)&p_sh1, g_sh1);
    cudaGetSymbolAddress((void**)&p_sc2, g_sc2);
    cudaGetSymbolAddress((void**)&p_sh2, g_sh2);

    const float invN = 1.0f / (float)n;
    const int nblk = (n + SCAN_CHUNK - 1) / SCAN_CHUNK;

    // ---- CSR build ----
    k_zero<<<(n + 255) / 256, 256>>>(p_cnt, p_sum1, p_sq1, p_sum2, p_sq2, n);
    k_count<<<(E + 255) / 256, 256>>>(dst, p_cnt, E);
    k_scan1<<<nblk, 256>>>(p_cnt, p_partial, n);
    k_scan2<<<1, 128>>>(p_partial, p_pscan, p_rowptr, nblk, n);
    k_scan3<<<nblk, 256>>>(p_cnt, p_pscan, p_rowptr, p_fill, p_dinv, n);
    k_fill<<<(E + 255) / 256, 256>>>(src, dst, p_dinv, p_fill, p_adjp, E);

    // ---- layer 1 ----
    k_gemm_tc<HID, 0, FEAT><<<(n + 127) / 128, 256>>>(
        features, W1, p_h1, n, nullptr, nullptr);
    k_aggr<HID><<<1184, 256>>>(p_rowptr, p_adjp, p_h1, p_dinv, b1,
                               p_x1, p_sum1, p_sq1, n);
    k_bnfin<<<1, 128>>>(p_sum1, p_sq1, gamma1, beta1, p_sc1, p_sh1, HID, invN);

    // ---- layer 2 (BN1+ReLU fused into GEMM A conversion) ----
    k_gemm_tc<OUTC, 1, HID><<<(n + 127) / 128, 256>>>(
        p_x1, W2, p_h2, n, p_sc1, p_sh1);
    k_aggr<OUTC><<<1184, 256>>>(p_rowptr, p_adjp, p_h2, p_dinv, b2,
                                p_x2, p_sum2, p_sq2, n);
    k_bnfin<<<1, 64>>>(p_sum2, p_sq2, gamma2, beta2, p_sc2, p_sh2, OUTC, invN);

    // ---- output ----
    k_out<<<(NB * 32 + 255) / 256, 256>>>(p_x2, batch, p_sc2, p_sh2, out, NB);
}